// round 1
// baseline (speedup 1.0000x reference)
#include <cuda_runtime.h>

#define T_SEQ   2048
#define NB      2
#define DIM     1024
#define NH      16
#define HS      64
#define NT_ROWS 4096
#define NEG_INF_F (-1e9f)
#define PAD     68

// Scratch (allocation-free rule: __device__ globals)
__device__ float g_Q[NT_ROWS * DIM];
__device__ float g_K[NT_ROWS * DIM];
__device__ float g_V[NT_ROWS * DIM];
__device__ float g_O[NT_ROWS * DIM];

// ---------------------------------------------------------------------------
// Tiled SGEMM: C[M,N] = scale * (A[M,K] @ B[K,N]), all row-major.
// BM=BN=128, BK=16, 256 threads, 8x8 microtile.
// ---------------------------------------------------------------------------
__global__ __launch_bounds__(256) void sgemm128(
    const float* __restrict__ A, const float* __restrict__ B,
    float* __restrict__ C, int M, int N, int K, float scale)
{
    __shared__ float As[16][128];   // transposed: As[k][m]
    __shared__ float Bs[16][128];
    const int tid = threadIdx.x;
    const int tx = tid & 15, ty = tid >> 4;
    const int bm = blockIdx.y * 128, bn = blockIdx.x * 128;

    float acc[8][8];
#pragma unroll
    for (int i = 0; i < 8; i++)
#pragma unroll
        for (int j = 0; j < 8; j++) acc[i][j] = 0.f;

    for (int k0 = 0; k0 < K; k0 += 16) {
#pragma unroll
        for (int i = tid; i < 512; i += 256) {
            int r = i >> 2, c = (i & 3) * 4;
            float4 v = *(const float4*)(A + (size_t)(bm + r) * K + k0 + c);
            As[c + 0][r] = v.x; As[c + 1][r] = v.y;
            As[c + 2][r] = v.z; As[c + 3][r] = v.w;
        }
#pragma unroll
        for (int i = tid; i < 512; i += 256) {
            int r = i >> 5, c = (i & 31) * 4;
            *(float4*)&Bs[r][c] = *(const float4*)(B + (size_t)(k0 + r) * N + bn + c);
        }
        __syncthreads();
#pragma unroll
        for (int k = 0; k < 16; k++) {
            float a[8], b[8];
            *(float4*)&a[0] = *(float4*)&As[k][ty * 8];
            *(float4*)&a[4] = *(float4*)&As[k][ty * 8 + 4];
            *(float4*)&b[0] = *(float4*)&Bs[k][tx * 8];
            *(float4*)&b[4] = *(float4*)&Bs[k][tx * 8 + 4];
#pragma unroll
            for (int i = 0; i < 8; i++)
#pragma unroll
                for (int j = 0; j < 8; j++)
                    acc[i][j] = fmaf(a[i], b[j], acc[i][j]);
        }
        __syncthreads();
    }
#pragma unroll
    for (int i = 0; i < 8; i++) {
        float4 o0 = make_float4(acc[i][0] * scale, acc[i][1] * scale,
                                acc[i][2] * scale, acc[i][3] * scale);
        float4 o1 = make_float4(acc[i][4] * scale, acc[i][5] * scale,
                                acc[i][6] * scale, acc[i][7] * scale);
        float* cp = C + (size_t)(bm + ty * 8 + i) * N + bn + tx * 8;
        *(float4*)cp       = o0;
        *(float4*)(cp + 4) = o1;
    }
}

// ---------------------------------------------------------------------------
// Flash attention: one block handles one (n, h, 64-row q-tile).
// Streams 64-row K/V tiles, online softmax, fused additive mask (mask*NEG_INF).
// 256 threads: thread (tx,ty) owns 4x4 score microtile (q=4ty.., r/c=4tx..).
// ---------------------------------------------------------------------------
__global__ __launch_bounds__(256) void attn_kernel(
    const float* __restrict__ gQ, const float* __restrict__ gK,
    const float* __restrict__ gV, const float* __restrict__ mask,
    float* __restrict__ gO)
{
    extern __shared__ float sm[];
    float* Qs = sm;               // [64][PAD]
    float* Ks = Qs + 64 * PAD;    // [64][PAD]
    float* Vs = Ks + 64 * PAD;    // [64][PAD]
    float* Ps = Vs + 64 * PAD;    // [64][PAD]

    const int tid = threadIdx.x;
    const int tx = tid & 15, ty = tid >> 4;
    const int qt = blockIdx.x, h = blockIdx.y, n = blockIdx.z;
    const int qbase = n * T_SEQ + qt * 64;
    const int col = h * HS;
    const float* mrow = mask + ((size_t)(n * NH + h) * T_SEQ + qt * 64) * T_SEQ;

    // Load Q tile (64 x 64)
    for (int i = tid; i < 64 * 16; i += 256) {
        int r = i >> 4, c = (i & 15) * 4;
        *(float4*)&Qs[r * PAD + c] =
            *(const float4*)(gQ + (size_t)(qbase + r) * DIM + col + c);
    }

    float m_i[4], l_i[4], accO[4][4];
#pragma unroll
    for (int i = 0; i < 4; i++) {
        m_i[i] = -1e30f; l_i[i] = 0.f;
#pragma unroll
        for (int j = 0; j < 4; j++) accO[i][j] = 0.f;
    }
    __syncthreads();

    for (int kt = 0; kt < T_SEQ / 64; kt++) {
        const int rbase = n * T_SEQ + kt * 64;
        for (int i = tid; i < 64 * 16; i += 256) {
            int r = i >> 4, c = (i & 15) * 4;
            *(float4*)&Ks[r * PAD + c] =
                *(const float4*)(gK + (size_t)(rbase + r) * DIM + col + c);
            *(float4*)&Vs[r * PAD + c] =
                *(const float4*)(gV + (size_t)(rbase + r) * DIM + col + c);
        }
        __syncthreads();

        // Scores: 4x4 microtile, dot over S=64
        float sc[4][4];
#pragma unroll
        for (int i = 0; i < 4; i++)
#pragma unroll
            for (int j = 0; j < 4; j++) sc[i][j] = 0.f;

#pragma unroll 8
        for (int k = 0; k < 64; k++) {
            float qv[4], kv[4];
#pragma unroll
            for (int i = 0; i < 4; i++) qv[i] = Qs[(ty * 4 + i) * PAD + k];
#pragma unroll
            for (int j = 0; j < 4; j++) kv[j] = Ks[(tx * 4 + j) * PAD + k];
#pragma unroll
            for (int i = 0; i < 4; i++)
#pragma unroll
                for (int j = 0; j < 4; j++)
                    sc[i][j] = fmaf(qv[i], kv[j], sc[i][j]);
        }

        // Additive mask: sc += mask * NEG_INF
#pragma unroll
        for (int i = 0; i < 4; i++) {
            float4 mv = *(const float4*)(mrow + (size_t)(ty * 4 + i) * T_SEQ
                                         + kt * 64 + tx * 4);
            sc[i][0] = fmaf(mv.x, NEG_INF_F, sc[i][0]);
            sc[i][1] = fmaf(mv.y, NEG_INF_F, sc[i][1]);
            sc[i][2] = fmaf(mv.z, NEG_INF_F, sc[i][2]);
            sc[i][3] = fmaf(mv.w, NEG_INF_F, sc[i][3]);
        }

        // Online softmax: row stats shared by the 16 tx-lanes of each q row
#pragma unroll
        for (int i = 0; i < 4; i++) {
            float mt = fmaxf(fmaxf(sc[i][0], sc[i][1]), fmaxf(sc[i][2], sc[i][3]));
#pragma unroll
            for (int off = 1; off < 16; off <<= 1)
                mt = fmaxf(mt, __shfl_xor_sync(0xffffffffu, mt, off));
            float mnew = fmaxf(m_i[i], mt);
            float corr = __expf(m_i[i] - mnew);
            float rs = 0.f;
#pragma unroll
            for (int j = 0; j < 4; j++) {
                float p = __expf(sc[i][j] - mnew);
                Ps[(ty * 4 + i) * PAD + tx * 4 + j] = p;
                rs += p;
            }
#pragma unroll
            for (int off = 1; off < 16; off <<= 1)
                rs += __shfl_xor_sync(0xffffffffu, rs, off);
            l_i[i] = l_i[i] * corr + rs;
            m_i[i] = mnew;
#pragma unroll
            for (int j = 0; j < 4; j++) accO[i][j] *= corr;
        }
        __syncthreads();

        // accO += P @ V  (c = 4*tx + j)
#pragma unroll 4
        for (int r = 0; r < 64; r++) {
            float4 vv = *(float4*)&Vs[r * PAD + tx * 4];
#pragma unroll
            for (int i = 0; i < 4; i++) {
                float p = Ps[(ty * 4 + i) * PAD + r];
                accO[i][0] = fmaf(p, vv.x, accO[i][0]);
                accO[i][1] = fmaf(p, vv.y, accO[i][1]);
                accO[i][2] = fmaf(p, vv.z, accO[i][2]);
                accO[i][3] = fmaf(p, vv.w, accO[i][3]);
            }
        }
        __syncthreads();
    }

    // Epilogue: normalize and store
#pragma unroll
    for (int i = 0; i < 4; i++) {
        float inv = 1.f / l_i[i];
        float4 o = make_float4(accO[i][0] * inv, accO[i][1] * inv,
                               accO[i][2] * inv, accO[i][3] * inv);
        *(float4*)(gO + (size_t)(qbase + ty * 4 + i) * DIM + col + tx * 4) = o;
    }
}

// ---------------------------------------------------------------------------
extern "C" void kernel_launch(void* const* d_in, const int* in_sizes, int n_in,
                              void* d_out, int out_size)
{
    const float* Xq   = (const float*)d_in[0];  // query_seqs   [2,2048,1024]
    const float* Xr   = (const float*)d_in[1];  // reference_seqs
    const float* mask = (const float*)d_in[2];  // token_mask [2,16,2048,2048]
    const float* Wq   = (const float*)d_in[3];  // [1024,16,64] == [1024,1024]
    const float* Wk   = (const float*)d_in[4];
    const float* Wv   = (const float*)d_in[5];
    const float* Wo   = (const float*)d_in[6];  // [16,64,1024] == [1024,1024]
    float* out = (float*)d_out;

    float *Qp, *Kp, *Vp, *Op;
    cudaGetSymbolAddress((void**)&Qp, g_Q);
    cudaGetSymbolAddress((void**)&Kp, g_K);
    cudaGetSymbolAddress((void**)&Vp, g_V);
    cudaGetSymbolAddress((void**)&Op, g_O);

    const int attn_smem = 4 * 64 * PAD * (int)sizeof(float);  // 69632 B
    cudaFuncSetAttribute(attn_kernel,
                         cudaFuncAttributeMaxDynamicSharedMemorySize, attn_smem);

    dim3 gp(DIM / 128, NT_ROWS / 128);
    // Q = Xq @ Wq * S^-0.5 ; K = Xr @ Wk ; V = Xr @ Wv
    sgemm128<<<gp, 256>>>(Xq, Wq, Qp, NT_ROWS, DIM, DIM, 0.125f);
    sgemm128<<<gp, 256>>>(Xr, Wk, Kp, NT_ROWS, DIM, DIM, 1.0f);
    sgemm128<<<gp, 256>>>(Xr, Wv, Vp, NT_ROWS, DIM, DIM, 1.0f);

    attn_kernel<<<dim3(T_SEQ / 64, NH, NB), 256, attn_smem>>>(Qp, Kp, Vp, mask, Op);

    // out = O @ Wo
    sgemm128<<<gp, 256>>>(Op, Wo, out, NT_ROWS, DIM, DIM, 1.0f);
}

// round 2
// speedup vs baseline: 2.6100x; 2.6100x over previous
#include <cuda_runtime.h>
#include <cuda_bf16.h>

#define T_SEQ 2048
#define NB 2
#define DIM 1024
#define NH 16
#define HS 64
#define NT_ROWS 4096
#define NEG_INF_F (-1e9f)
#define NELEM (NT_ROWS * DIM)

// ---------------- scratch (__device__ globals: allocation-free rule) --------
__device__ __nv_bfloat16 g_Xqh[NELEM], g_Xql[NELEM];
__device__ __nv_bfloat16 g_Xrh[NELEM], g_Xrl[NELEM];
__device__ __nv_bfloat16 g_Wqh[DIM * DIM], g_Wql[DIM * DIM];
__device__ __nv_bfloat16 g_Wkh[DIM * DIM], g_Wkl[DIM * DIM];
__device__ __nv_bfloat16 g_Wvh[DIM * DIM], g_Wvl[DIM * DIM];
__device__ __nv_bfloat16 g_Woh[DIM * DIM], g_Wol[DIM * DIM];
__device__ __nv_bfloat16 g_Qh[NELEM], g_Ql[NELEM];
__device__ __nv_bfloat16 g_Kh[NELEM], g_Kl[NELEM];
__device__ __nv_bfloat16 g_Vh[NELEM], g_Vl[NELEM];
__device__ __nv_bfloat16 g_Vth[NELEM], g_Vtl[NELEM];
__device__ __nv_bfloat16 g_Oh[NELEM], g_Ol[NELEM];

// ---------------- helpers ---------------------------------------------------
__device__ __forceinline__ void split2(float x, __nv_bfloat16& h, __nv_bfloat16& l) {
    h = __float2bfloat16(x);
    l = __float2bfloat16(x - __bfloat162float(h));
}
__device__ __forceinline__ unsigned pk(__nv_bfloat16 a, __nv_bfloat16 b) {
    return (unsigned)__bfloat16_as_ushort(a) | ((unsigned)__bfloat16_as_ushort(b) << 16);
}
__device__ __forceinline__ void split_pack2(float x0, float x1, unsigned& ph, unsigned& pl) {
    __nv_bfloat16 h0, l0, h1, l1;
    split2(x0, h0, l0);
    split2(x1, h1, l1);
    ph = pk(h0, h1);
    pl = pk(l0, l1);
}
// D += A(16x16 bf16, row) * B(16x8 bf16, col), fp32 accum
__device__ __forceinline__ void mma16816(float (&d)[4], const unsigned (&a)[4],
                                         unsigned b0, unsigned b1) {
    asm volatile(
        "mma.sync.aligned.m16n8k16.row.col.f32.bf16.bf16.f32 "
        "{%0,%1,%2,%3}, {%4,%5,%6,%7}, {%8,%9}, {%0,%1,%2,%3};"
        : "+f"(d[0]), "+f"(d[1]), "+f"(d[2]), "+f"(d[3])
        : "r"(a[0]), "r"(a[1]), "r"(a[2]), "r"(a[3]), "r"(b0), "r"(b1));
}

// ---------------- split kernels ---------------------------------------------
// X [rows][1024] f32 -> hi/lo bf16, same layout
__global__ __launch_bounds__(256) void split_x(const float* __restrict__ X,
                                               __nv_bfloat16* __restrict__ Xh,
                                               __nv_bfloat16* __restrict__ Xl) {
    size_t i = ((size_t)blockIdx.x * 256 + threadIdx.x) * 4;
    float4 v = *(const float4*)(X + i);
    __nv_bfloat16 h0, l0, h1, l1, h2, l2, h3, l3;
    split2(v.x, h0, l0); split2(v.y, h1, l1);
    split2(v.z, h2, l2); split2(v.w, h3, l3);
    *(unsigned*)&Xh[i]     = pk(h0, h1);
    *(unsigned*)&Xh[i + 2] = pk(h2, h3);
    *(unsigned*)&Xl[i]     = pk(l0, l1);
    *(unsigned*)&Xl[i + 2] = pk(l2, l3);
}

// W [k=1024][n=1024] f32 -> Wt hi/lo [n][k] bf16 (transposed)
__global__ __launch_bounds__(256) void split_wT(const float* __restrict__ W,
                                                __nv_bfloat16* __restrict__ Wth,
                                                __nv_bfloat16* __restrict__ Wtl) {
    __shared__ float S[32][33];
    const int n0 = blockIdx.x * 32, k0 = blockIdx.y * 32;
    const int tid = threadIdx.x;
#pragma unroll
    for (int i = tid; i < 1024; i += 256) {
        int r = i >> 5, c = i & 31;  // r: k-offset, c: n-offset
        S[r][c] = W[(size_t)(k0 + r) * DIM + n0 + c];
    }
    __syncthreads();
#pragma unroll
    for (int i = tid; i < 1024; i += 256) {
        int rr = i >> 5, cc = i & 31;  // rr: n-offset, cc: k-offset
        __nv_bfloat16 h, l;
        split2(S[cc][rr], h, l);
        Wth[(size_t)(n0 + rr) * DIM + k0 + cc] = h;
        Wtl[(size_t)(n0 + rr) * DIM + k0 + cc] = l;
    }
}

// V hi/lo [4096][1024] -> Vt hi/lo [(b,h,s)=2048 rows][2048 tokens]
__global__ __launch_bounds__(256) void transpose_v(const __nv_bfloat16* __restrict__ Vh,
                                                   const __nv_bfloat16* __restrict__ Vl,
                                                   __nv_bfloat16* __restrict__ Vth,
                                                   __nv_bfloat16* __restrict__ Vtl) {
    __shared__ __nv_bfloat16 Sh[64][66], Sl[64][66];
    const int tt = blockIdx.x, bh = blockIdx.y;  // bh = b*16+h
    const int b = bh >> 4, h = bh & 15;
    const int tid = threadIdx.x;
#pragma unroll
    for (int i = tid; i < 64 * 32; i += 256) {
        int r = i >> 5, c2 = (i & 31) * 2;  // r = token, c2 = s
        size_t g = (size_t)(b * T_SEQ + tt * 64 + r) * DIM + h * HS + c2;
        *(unsigned*)&Sh[r][c2] = *(const unsigned*)&Vh[g];
        *(unsigned*)&Sl[r][c2] = *(const unsigned*)&Vl[g];
    }
    __syncthreads();
#pragma unroll
    for (int i = tid; i < 64 * 32; i += 256) {
        int s = i >> 5, t2 = (i & 31) * 2;
        size_t g = (size_t)(bh * HS + s) * T_SEQ + tt * 64 + t2;
        *(unsigned*)&Vth[g] = pk(Sh[t2][s], Sh[t2 + 1][s]);
        *(unsigned*)&Vtl[g] = pk(Sl[t2][s], Sl[t2 + 1][s]);
    }
}

// ---------------- split-bf16 MMA GEMM ---------------------------------------
// C[4096,1024] = scale * (A @ B), A hi/lo [m][k] bf16, Bt hi/lo [n][k] bf16.
// mode 0: Cf fp32 out; mode 1: Ch/Cl split-bf16 out.
#define GP 40  // smem pitch (bf16 elems) for 32-wide k tiles
__global__ __launch_bounds__(256) void gemm_mma(
    const __nv_bfloat16* __restrict__ Ah_, const __nv_bfloat16* __restrict__ Al_,
    const __nv_bfloat16* __restrict__ Bh_, const __nv_bfloat16* __restrict__ Bl_,
    float* __restrict__ Cf, __nv_bfloat16* __restrict__ Ch,
    __nv_bfloat16* __restrict__ Cl, int mode, float scale) {
    __shared__ __nv_bfloat16 As_h[128][GP], As_l[128][GP];
    __shared__ __nv_bfloat16 Bs_h[128][GP], Bs_l[128][GP];
    const int tid = threadIdx.x;
    const int lane = tid & 31, wid = tid >> 5;
    const int gid = lane >> 2, tig = lane & 3;
    const int wm = (wid & 3) * 32, wn = (wid >> 2) * 64;
    const int bm = blockIdx.y * 128, bn = blockIdx.x * 128;

    float acc[2][8][4];
#pragma unroll
    for (int mt = 0; mt < 2; mt++)
#pragma unroll
        for (int jn = 0; jn < 8; jn++)
#pragma unroll
            for (int e = 0; e < 4; e++) acc[mt][jn][e] = 0.f;

    for (int k0 = 0; k0 < DIM; k0 += 32) {
#pragma unroll
        for (int i = tid; i < 512; i += 256) {
            int r = i >> 2, c8 = (i & 3) * 8;
            *(int4*)&As_h[r][c8] = *(const int4*)(Ah_ + (size_t)(bm + r) * DIM + k0 + c8);
            *(int4*)&As_l[r][c8] = *(const int4*)(Al_ + (size_t)(bm + r) * DIM + k0 + c8);
            *(int4*)&Bs_h[r][c8] = *(const int4*)(Bh_ + (size_t)(bn + r) * DIM + k0 + c8);
            *(int4*)&Bs_l[r][c8] = *(const int4*)(Bl_ + (size_t)(bn + r) * DIM + k0 + c8);
        }
        __syncthreads();
#pragma unroll
        for (int kk = 0; kk < 2; kk++) {
            const int kc = kk * 16 + 2 * tig;
            unsigned ah[2][4], al[2][4];
#pragma unroll
            for (int mt = 0; mt < 2; mt++) {
                int row = wm + 16 * mt + gid;
                ah[mt][0] = *(const unsigned*)&As_h[row][kc];
                ah[mt][1] = *(const unsigned*)&As_h[row + 8][kc];
                ah[mt][2] = *(const unsigned*)&As_h[row][kc + 8];
                ah[mt][3] = *(const unsigned*)&As_h[row + 8][kc + 8];
                al[mt][0] = *(const unsigned*)&As_l[row][kc];
                al[mt][1] = *(const unsigned*)&As_l[row + 8][kc];
                al[mt][2] = *(const unsigned*)&As_l[row][kc + 8];
                al[mt][3] = *(const unsigned*)&As_l[row + 8][kc + 8];
            }
#pragma unroll
            for (int jn = 0; jn < 8; jn++) {
                int n = wn + 8 * jn + gid;
                unsigned bh0 = *(const unsigned*)&Bs_h[n][kc];
                unsigned bh1 = *(const unsigned*)&Bs_h[n][kc + 8];
                unsigned bl0 = *(const unsigned*)&Bs_l[n][kc];
                unsigned bl1 = *(const unsigned*)&Bs_l[n][kc + 8];
#pragma unroll
                for (int mt = 0; mt < 2; mt++) {
                    mma16816(acc[mt][jn], ah[mt], bh0, bh1);
                    mma16816(acc[mt][jn], ah[mt], bl0, bl1);
                    mma16816(acc[mt][jn], al[mt], bh0, bh1);
                }
            }
        }
        __syncthreads();
    }
#pragma unroll
    for (int mt = 0; mt < 2; mt++) {
        int row0 = bm + wm + 16 * mt + gid;
#pragma unroll
        for (int jn = 0; jn < 8; jn++) {
            int col = bn + wn + 8 * jn + 2 * tig;
            float x0 = acc[mt][jn][0] * scale, x1 = acc[mt][jn][1] * scale;
            float x2 = acc[mt][jn][2] * scale, x3 = acc[mt][jn][3] * scale;
            if (mode == 0) {
                *(float2*)&Cf[(size_t)row0 * DIM + col] = make_float2(x0, x1);
                *(float2*)&Cf[(size_t)(row0 + 8) * DIM + col] = make_float2(x2, x3);
            } else {
                unsigned ph, pl;
                split_pack2(x0, x1, ph, pl);
                *(unsigned*)&Ch[(size_t)row0 * DIM + col] = ph;
                *(unsigned*)&Cl[(size_t)row0 * DIM + col] = pl;
                split_pack2(x2, x3, ph, pl);
                *(unsigned*)&Ch[(size_t)(row0 + 8) * DIM + col] = ph;
                *(unsigned*)&Cl[(size_t)(row0 + 8) * DIM + col] = pl;
            }
        }
    }
}

// ---------------- flash attention with MMA ----------------------------------
// Block: 256 thr (8 warps), Br=128 q rows, Bc=64 kv tokens per iter.
// Warp w owns q rows [16w,16w+16). grid (16 qtiles, 16 heads, 2 batch).
#define AP 72  // smem pitch (bf16) for 64-wide tiles
__global__ __launch_bounds__(256) void attn_mma(
    const __nv_bfloat16* __restrict__ Qh_, const __nv_bfloat16* __restrict__ Ql_,
    const __nv_bfloat16* __restrict__ Kh_, const __nv_bfloat16* __restrict__ Kl_,
    const __nv_bfloat16* __restrict__ Vth_, const __nv_bfloat16* __restrict__ Vtl_,
    const float* __restrict__ mask,
    __nv_bfloat16* __restrict__ Oh_, __nv_bfloat16* __restrict__ Ol_) {
    extern __shared__ char smraw[];
    __nv_bfloat16* Qh = (__nv_bfloat16*)smraw;  // [128][AP]
    __nv_bfloat16* Ql = Qh + 128 * AP;
    __nv_bfloat16* Kh = Ql + 128 * AP;          // [64][AP]
    __nv_bfloat16* Kl = Kh + 64 * AP;
    __nv_bfloat16* Vh = Kl + 64 * AP;           // [64][AP] (rows=s, cols=token)
    __nv_bfloat16* Vl = Vh + 64 * AP;

    const int tid = threadIdx.x;
    const int lane = tid & 31, wid = tid >> 5;
    const int gid = lane >> 2, tig = lane & 3;
    const int bq = blockIdx.x, h = blockIdx.y, b = blockIdx.z;
    const int bh = b * NH + h;
    const int qrow0 = b * T_SEQ + bq * 128;

    // load Q tile (hi/lo)
#pragma unroll
    for (int i = tid; i < 128 * 8; i += 256) {
        int r = i >> 3, c8 = (i & 7) * 8;
        size_t g = (size_t)(qrow0 + r) * DIM + h * HS + c8;
        *(int4*)&Qh[r * AP + c8] = *(const int4*)&Qh_[g];
        *(int4*)&Ql[r * AP + c8] = *(const int4*)&Ql_[g];
    }

    float mi[2] = {-1e30f, -1e30f}, li[2] = {0.f, 0.f};
    float accO[8][4];
#pragma unroll
    for (int jn = 0; jn < 8; jn++)
#pragma unroll
        for (int e = 0; e < 4; e++) accO[jn][e] = 0.f;

    const int q0g = bq * 128 + 16 * wid + gid;  // global q row (within b,h)
    const float* mrow = mask + (size_t)bh * T_SEQ * T_SEQ;
    __syncthreads();

    for (int kt = 0; kt < T_SEQ / 64; kt++) {
        const int krow0 = b * T_SEQ + kt * 64;
#pragma unroll
        for (int i = tid; i < 64 * 8; i += 256) {
            int r = i >> 3, c8 = (i & 7) * 8;
            size_t gk = (size_t)(krow0 + r) * DIM + h * HS + c8;
            *(int4*)&Kh[r * AP + c8] = *(const int4*)&Kh_[gk];
            *(int4*)&Kl[r * AP + c8] = *(const int4*)&Kl_[gk];
            size_t gv = (size_t)(bh * HS + r) * T_SEQ + kt * 64 + c8;
            *(int4*)&Vh[r * AP + c8] = *(const int4*)&Vth_[gv];
            *(int4*)&Vl[r * AP + c8] = *(const int4*)&Vtl_[gv];
        }
        __syncthreads();

        // ---- scores: S = Q @ K^T (split-bf16, fp32 accum) ----
        float sc[8][4];
#pragma unroll
        for (int jn = 0; jn < 8; jn++)
#pragma unroll
            for (int e = 0; e < 4; e++) sc[jn][e] = 0.f;
#pragma unroll
        for (int kk = 0; kk < 4; kk++) {
            const int kc = kk * 16 + 2 * tig;
            const int row = 16 * wid + gid;
            unsigned qah[4], qal[4];
            qah[0] = *(const unsigned*)&Qh[row * AP + kc];
            qah[1] = *(const unsigned*)&Qh[(row + 8) * AP + kc];
            qah[2] = *(const unsigned*)&Qh[row * AP + kc + 8];
            qah[3] = *(const unsigned*)&Qh[(row + 8) * AP + kc + 8];
            qal[0] = *(const unsigned*)&Ql[row * AP + kc];
            qal[1] = *(const unsigned*)&Ql[(row + 8) * AP + kc];
            qal[2] = *(const unsigned*)&Ql[row * AP + kc + 8];
            qal[3] = *(const unsigned*)&Ql[(row + 8) * AP + kc + 8];
#pragma unroll
            for (int jn = 0; jn < 8; jn++) {
                int n = 8 * jn + gid;
                unsigned bh0 = *(const unsigned*)&Kh[n * AP + kc];
                unsigned bh1 = *(const unsigned*)&Kh[n * AP + kc + 8];
                unsigned bl0 = *(const unsigned*)&Kl[n * AP + kc];
                unsigned bl1 = *(const unsigned*)&Kl[n * AP + kc + 8];
                mma16816(sc[jn], qah, bh0, bh1);
                mma16816(sc[jn], qah, bl0, bl1);
                mma16816(sc[jn], qal, bh0, bh1);
            }
        }

        // ---- mask (coalesced float2 fragment loads) ----
#pragma unroll
        for (int jn = 0; jn < 8; jn++) {
            int c = kt * 64 + 8 * jn + 2 * tig;
            float2 m0 = *(const float2*)&mrow[(size_t)q0g * T_SEQ + c];
            float2 m1 = *(const float2*)&mrow[(size_t)(q0g + 8) * T_SEQ + c];
            sc[jn][0] = fmaf(m0.x, NEG_INF_F, sc[jn][0]);
            sc[jn][1] = fmaf(m0.y, NEG_INF_F, sc[jn][1]);
            sc[jn][2] = fmaf(m1.x, NEG_INF_F, sc[jn][2]);
            sc[jn][3] = fmaf(m1.y, NEG_INF_F, sc[jn][3]);
        }

        // ---- online softmax (rows: gid and gid+8 of this warp) ----
        float mx0 = -1e30f, mx1 = -1e30f;
#pragma unroll
        for (int jn = 0; jn < 8; jn++) {
            mx0 = fmaxf(mx0, fmaxf(sc[jn][0], sc[jn][1]));
            mx1 = fmaxf(mx1, fmaxf(sc[jn][2], sc[jn][3]));
        }
        mx0 = fmaxf(mx0, __shfl_xor_sync(0xffffffffu, mx0, 1));
        mx0 = fmaxf(mx0, __shfl_xor_sync(0xffffffffu, mx0, 2));
        mx1 = fmaxf(mx1, __shfl_xor_sync(0xffffffffu, mx1, 1));
        mx1 = fmaxf(mx1, __shfl_xor_sync(0xffffffffu, mx1, 2));
        float mn0 = fmaxf(mi[0], mx0), mn1 = fmaxf(mi[1], mx1);
        float corr0 = __expf(mi[0] - mn0), corr1 = __expf(mi[1] - mn1);
        mi[0] = mn0; mi[1] = mn1;
        float rs0 = 0.f, rs1 = 0.f;
#pragma unroll
        for (int jn = 0; jn < 8; jn++) {
            sc[jn][0] = __expf(sc[jn][0] - mn0); rs0 += sc[jn][0];
            sc[jn][1] = __expf(sc[jn][1] - mn0); rs0 += sc[jn][1];
            sc[jn][2] = __expf(sc[jn][2] - mn1); rs1 += sc[jn][2];
            sc[jn][3] = __expf(sc[jn][3] - mn1); rs1 += sc[jn][3];
        }
        rs0 += __shfl_xor_sync(0xffffffffu, rs0, 1);
        rs0 += __shfl_xor_sync(0xffffffffu, rs0, 2);
        rs1 += __shfl_xor_sync(0xffffffffu, rs1, 1);
        rs1 += __shfl_xor_sync(0xffffffffu, rs1, 2);
        li[0] = li[0] * corr0 + rs0;
        li[1] = li[1] * corr1 + rs1;
#pragma unroll
        for (int jn = 0; jn < 8; jn++) {
            accO[jn][0] *= corr0; accO[jn][1] *= corr0;
            accO[jn][2] *= corr1; accO[jn][3] *= corr1;
        }

        // ---- accO += P @ V (P fragments built in-register) ----
#pragma unroll
        for (int kk2 = 0; kk2 < 4; kk2++) {
            const int j0 = 2 * kk2, j1 = 2 * kk2 + 1;
            unsigned pah[4], pal[4];
            split_pack2(sc[j0][0], sc[j0][1], pah[0], pal[0]);
            split_pack2(sc[j0][2], sc[j0][3], pah[1], pal[1]);
            split_pack2(sc[j1][0], sc[j1][1], pah[2], pal[2]);
            split_pack2(sc[j1][2], sc[j1][3], pah[3], pal[3]);
            const int kc = kk2 * 16 + 2 * tig;
#pragma unroll
            for (int jn = 0; jn < 8; jn++) {
                int n = 8 * jn + gid;  // n = s index
                unsigned vh0 = *(const unsigned*)&Vh[n * AP + kc];
                unsigned vh1 = *(const unsigned*)&Vh[n * AP + kc + 8];
                unsigned vl0 = *(const unsigned*)&Vl[n * AP + kc];
                unsigned vl1 = *(const unsigned*)&Vl[n * AP + kc + 8];
                mma16816(accO[jn], pah, vh0, vh1);
                mma16816(accO[jn], pah, vl0, vl1);
                mma16816(accO[jn], pal, vh0, vh1);
            }
        }
        __syncthreads();
    }

    // ---- epilogue: normalize, split, store ----
    const float inv0 = 1.f / li[0], inv1 = 1.f / li[1];
    const int row0 = qrow0 + 16 * wid + gid;
#pragma unroll
    for (int jn = 0; jn < 8; jn++) {
        int col = h * HS + 8 * jn + 2 * tig;
        unsigned ph, pl;
        split_pack2(accO[jn][0] * inv0, accO[jn][1] * inv0, ph, pl);
        *(unsigned*)&Oh_[(size_t)row0 * DIM + col] = ph;
        *(unsigned*)&Ol_[(size_t)row0 * DIM + col] = pl;
        split_pack2(accO[jn][2] * inv1, accO[jn][3] * inv1, ph, pl);
        *(unsigned*)&Oh_[(size_t)(row0 + 8) * DIM + col] = ph;
        *(unsigned*)&Ol_[(size_t)(row0 + 8) * DIM + col] = pl;
    }
}

// ---------------------------------------------------------------------------
extern "C" void kernel_launch(void* const* d_in, const int* in_sizes, int n_in,
                              void* d_out, int out_size) {
    const float* Xq   = (const float*)d_in[0];
    const float* Xr   = (const float*)d_in[1];
    const float* mask = (const float*)d_in[2];
    const float* Wq   = (const float*)d_in[3];
    const float* Wk   = (const float*)d_in[4];
    const float* Wv   = (const float*)d_in[5];
    const float* Wo   = (const float*)d_in[6];
    float* out = (float*)d_out;

    __nv_bfloat16 *Xqh, *Xql, *Xrh, *Xrl;
    __nv_bfloat16 *Wqh, *Wql, *Wkh, *Wkl, *Wvh, *Wvl, *Woh, *Wol;
    __nv_bfloat16 *Qh, *Ql, *Kh, *Kl, *Vh, *Vl, *Vth, *Vtl, *Oh, *Ol;
    cudaGetSymbolAddress((void**)&Xqh, g_Xqh); cudaGetSymbolAddress((void**)&Xql, g_Xql);
    cudaGetSymbolAddress((void**)&Xrh, g_Xrh); cudaGetSymbolAddress((void**)&Xrl, g_Xrl);
    cudaGetSymbolAddress((void**)&Wqh, g_Wqh); cudaGetSymbolAddress((void**)&Wql, g_Wql);
    cudaGetSymbolAddress((void**)&Wkh, g_Wkh); cudaGetSymbolAddress((void**)&Wkl, g_Wkl);
    cudaGetSymbolAddress((void**)&Wvh, g_Wvh); cudaGetSymbolAddress((void**)&Wvl, g_Wvl);
    cudaGetSymbolAddress((void**)&Woh, g_Woh); cudaGetSymbolAddress((void**)&Wol, g_Wol);
    cudaGetSymbolAddress((void**)&Qh, g_Qh);   cudaGetSymbolAddress((void**)&Ql, g_Ql);
    cudaGetSymbolAddress((void**)&Kh, g_Kh);   cudaGetSymbolAddress((void**)&Kl, g_Kl);
    cudaGetSymbolAddress((void**)&Vh, g_Vh);   cudaGetSymbolAddress((void**)&Vl, g_Vl);
    cudaGetSymbolAddress((void**)&Vth, g_Vth); cudaGetSymbolAddress((void**)&Vtl, g_Vtl);
    cudaGetSymbolAddress((void**)&Oh, g_Oh);   cudaGetSymbolAddress((void**)&Ol, g_Ol);

    const int attn_smem = (2 * 128 + 4 * 64) * AP * 2;  // 73728 B
    cudaFuncSetAttribute(attn_mma, cudaFuncAttributeMaxDynamicSharedMemorySize, attn_smem);

    // 1) split inputs
    split_x<<<NELEM / 1024, 256>>>(Xq, Xqh, Xql);
    split_x<<<NELEM / 1024, 256>>>(Xr, Xrh, Xrl);
    dim3 gw(32, 32);
    split_wT<<<gw, 256>>>(Wq, Wqh, Wql);
    split_wT<<<gw, 256>>>(Wk, Wkh, Wkl);
    split_wT<<<gw, 256>>>(Wv, Wvh, Wvl);
    split_wT<<<gw, 256>>>(Wo, Woh, Wol);

    // 2) projections (split-bf16 outputs), Q scaled by S^-0.5
    dim3 gg(DIM / 128, NT_ROWS / 128);
    gemm_mma<<<gg, 256>>>(Xqh, Xql, Wqh, Wql, nullptr, Qh, Ql, 1, 0.125f);
    gemm_mma<<<gg, 256>>>(Xrh, Xrl, Wkh, Wkl, nullptr, Kh, Kl, 1, 1.0f);
    gemm_mma<<<gg, 256>>>(Xrh, Xrl, Wvh, Wvl, nullptr, Vh, Vl, 1, 1.0f);

    // 3) V transpose for PV fragment layout
    transpose_v<<<dim3(T_SEQ / 64, NB * NH), 256>>>(Vh, Vl, Vth, Vtl);

    // 4) flash attention (MMA)
    attn_mma<<<dim3(T_SEQ / 128, NH, NB), 256, attn_smem>>>(
        Qh, Ql, Kh, Kl, Vth, Vtl, mask, Oh, Ol);

    // 5) output projection -> fp32 d_out
    gemm_mma<<<gg, 256>>>(Oh, Ol, Woh, Wol, out, nullptr, nullptr, 0, 1.0f);
}

// round 4
// speedup vs baseline: 2.9196x; 1.1186x over previous
#include <cuda_runtime.h>
#include <cuda_bf16.h>
#include <cstdint>

#define T_SEQ 2048
#define NB 2
#define DIM 1024
#define NH 16
#define HS 64
#define NT_ROWS 4096
#define NEG_INF_F (-1e9f)
#define NELEM (NT_ROWS * DIM)

// ---------------- scratch (__device__ globals: allocation-free rule) --------
__device__ __nv_bfloat16 g_Xqh[NELEM], g_Xql[NELEM];
__device__ __nv_bfloat16 g_Xrh[NELEM], g_Xrl[NELEM];
__device__ __nv_bfloat16 g_Wqh[DIM * DIM], g_Wql[DIM * DIM];
__device__ __nv_bfloat16 g_Wkh[DIM * DIM], g_Wkl[DIM * DIM];
__device__ __nv_bfloat16 g_Wvh[DIM * DIM], g_Wvl[DIM * DIM];
__device__ __nv_bfloat16 g_Woh[DIM * DIM], g_Wol[DIM * DIM];
__device__ __nv_bfloat16 g_Qh[NELEM], g_Ql[NELEM];
__device__ __nv_bfloat16 g_Kh[NELEM], g_Kl[NELEM];
__device__ __nv_bfloat16 g_Vh[NELEM], g_Vl[NELEM];
__device__ __nv_bfloat16 g_Vth[NELEM], g_Vtl[NELEM];
__device__ __nv_bfloat16 g_Oh[NELEM], g_Ol[NELEM];

// ---------------- helpers ---------------------------------------------------
__device__ __forceinline__ void split2(float x, __nv_bfloat16& h, __nv_bfloat16& l) {
    h = __float2bfloat16(x);
    l = __float2bfloat16(x - __bfloat162float(h));
}
__device__ __forceinline__ unsigned pk(__nv_bfloat16 a, __nv_bfloat16 b) {
    return (unsigned)__bfloat16_as_ushort(a) | ((unsigned)__bfloat16_as_ushort(b) << 16);
}
__device__ __forceinline__ void split_pack2(float x0, float x1, unsigned& ph, unsigned& pl) {
    __nv_bfloat16 h0, l0, h1, l1;
    split2(x0, h0, l0);
    split2(x1, h1, l1);
    ph = pk(h0, h1);
    pl = pk(l0, l1);
}
__device__ __forceinline__ void mma16816(float (&d)[4], const unsigned (&a)[4],
                                         unsigned b0, unsigned b1) {
    asm volatile(
        "mma.sync.aligned.m16n8k16.row.col.f32.bf16.bf16.f32 "
        "{%0,%1,%2,%3}, {%4,%5,%6,%7}, {%8,%9}, {%0,%1,%2,%3};"
        : "+f"(d[0]), "+f"(d[1]), "+f"(d[2]), "+f"(d[3])
        : "r"(a[0]), "r"(a[1]), "r"(a[2]), "r"(a[3]), "r"(b0), "r"(b1));
}
__device__ __forceinline__ uint32_t smem_u32(const void* p) {
    uint32_t a;
    asm("{ .reg .u64 t; cvta.to.shared.u64 t, %1; cvt.u32.u64 %0, t; }" : "=r"(a) : "l"(p));
    return a;
}
__device__ __forceinline__ void cp16(void* smem_dst, const void* gsrc) {
    uint32_t s = smem_u32(smem_dst);
    asm volatile("cp.async.cg.shared.global [%0], [%1], 16;" :: "r"(s), "l"(gsrc) : "memory");
}
#define CP_COMMIT() asm volatile("cp.async.commit_group;" ::: "memory")
#define CP_WAIT1() asm volatile("cp.async.wait_group 1;" ::: "memory")

// ---------------- split kernels ---------------------------------------------
__global__ __launch_bounds__(256) void split_x(const float* __restrict__ X,
                                               __nv_bfloat16* __restrict__ Xh,
                                               __nv_bfloat16* __restrict__ Xl) {
    size_t i = ((size_t)blockIdx.x * 256 + threadIdx.x) * 4;
    float4 v = *(const float4*)(X + i);
    __nv_bfloat16 h0, l0, h1, l1, h2, l2, h3, l3;
    split2(v.x, h0, l0); split2(v.y, h1, l1);
    split2(v.z, h2, l2); split2(v.w, h3, l3);
    *(unsigned*)&Xh[i]     = pk(h0, h1);
    *(unsigned*)&Xh[i + 2] = pk(h2, h3);
    *(unsigned*)&Xl[i]     = pk(l0, l1);
    *(unsigned*)&Xl[i + 2] = pk(l2, l3);
}

__global__ __launch_bounds__(256) void split_wT(const float* __restrict__ W,
                                                __nv_bfloat16* __restrict__ Wth,
                                                __nv_bfloat16* __restrict__ Wtl) {
    __shared__ float S[32][33];
    const int n0 = blockIdx.x * 32, k0 = blockIdx.y * 32;
    const int tid = threadIdx.x;
#pragma unroll
    for (int i = tid; i < 1024; i += 256) {
        int r = i >> 5, c = i & 31;
        S[r][c] = W[(size_t)(k0 + r) * DIM + n0 + c];
    }
    __syncthreads();
#pragma unroll
    for (int i = tid; i < 1024; i += 256) {
        int rr = i >> 5, cc = i & 31;
        __nv_bfloat16 h, l;
        split2(S[cc][rr], h, l);
        Wth[(size_t)(n0 + rr) * DIM + k0 + cc] = h;
        Wtl[(size_t)(n0 + rr) * DIM + k0 + cc] = l;
    }
}

__global__ __launch_bounds__(256) void transpose_v(const __nv_bfloat16* __restrict__ Vh,
                                                   const __nv_bfloat16* __restrict__ Vl,
                                                   __nv_bfloat16* __restrict__ Vth,
                                                   __nv_bfloat16* __restrict__ Vtl) {
    __shared__ __nv_bfloat16 Sh[64][66], Sl[64][66];
    const int tt = blockIdx.x, bh = blockIdx.y;
    const int b = bh >> 4, h = bh & 15;
    const int tid = threadIdx.x;
#pragma unroll
    for (int i = tid; i < 64 * 32; i += 256) {
        int r = i >> 5, c2 = (i & 31) * 2;
        size_t g = (size_t)(b * T_SEQ + tt * 64 + r) * DIM + h * HS + c2;
        *(unsigned*)&Sh[r][c2] = *(const unsigned*)&Vh[g];
        *(unsigned*)&Sl[r][c2] = *(const unsigned*)&Vl[g];
    }
    __syncthreads();
#pragma unroll
    for (int i = tid; i < 64 * 32; i += 256) {
        int s = i >> 5, t2 = (i & 31) * 2;
        size_t g = (size_t)(bh * HS + s) * T_SEQ + tt * 64 + t2;
        *(unsigned*)&Vth[g] = pk(Sh[t2][s], Sh[t2 + 1][s]);
        *(unsigned*)&Vtl[g] = pk(Sl[t2][s], Sl[t2 + 1][s]);
    }
}

// ---------------- split-bf16 MMA GEMM, cp.async double-buffered --------------
// C[4096,1024] = scale*(A@B); A hi/lo [m][k], Bt hi/lo [n][k]. 128x128x32 tiles.
#define GP 40                     // smem pitch (bf16) for 32-wide k tiles
#define GEMM_NKT 32               // 1024/32
#define GEMM_SMEM (8 * 128 * GP * 2)   // 2 stages x 4 arrays = 81920 B

__global__ __launch_bounds__(256) void gemm_mma(
    const __nv_bfloat16* __restrict__ Ah_, const __nv_bfloat16* __restrict__ Al_,
    const __nv_bfloat16* __restrict__ Bh_, const __nv_bfloat16* __restrict__ Bl_,
    float* __restrict__ Cf, __nv_bfloat16* __restrict__ Ch,
    __nv_bfloat16* __restrict__ Cl, int mode, float scale) {
    extern __shared__ __nv_bfloat16 gsm[];
    const int tid = threadIdx.x;
    const int lane = tid & 31, wid = tid >> 5;
    const int gid = lane >> 2, tig = lane & 3;
    const int wm = (wid & 3) * 32, wn = (wid >> 2) * 64;
    const int bm = blockIdx.y * 128, bn = blockIdx.x * 128;

    const __nv_bfloat16* srcs[4] = {Ah_, Al_, Bh_, Bl_};

    // stage s, array a at gsm + ((s*4+a)*128*GP)
    auto load_stage = [&](int stage, int kt) {
        const int k0 = kt * 32;
        __nv_bfloat16* sb = gsm + stage * 4 * 128 * GP;
#pragma unroll
        for (int i = tid; i < 2048; i += 256) {
            int a = i >> 9, r = (i >> 2) & 127, c = i & 3;
            const int rbase = (a < 2) ? bm : bn;
            cp16(sb + a * 128 * GP + r * GP + c * 8,
                 srcs[a] + (size_t)(rbase + r) * DIM + k0 + c * 8);
        }
    };

    float acc[2][8][4];
#pragma unroll
    for (int mt = 0; mt < 2; mt++)
#pragma unroll
        for (int jn = 0; jn < 8; jn++)
#pragma unroll
            for (int e = 0; e < 4; e++) acc[mt][jn][e] = 0.f;

    load_stage(0, 0); CP_COMMIT();
    load_stage(1, 1); CP_COMMIT();

    for (int kt = 0; kt < GEMM_NKT; kt++) {
        const int cur = kt & 1;
        CP_WAIT1();
        __syncthreads();
        const __nv_bfloat16* As_h = gsm + (cur * 4 + 0) * 128 * GP;
        const __nv_bfloat16* As_l = gsm + (cur * 4 + 1) * 128 * GP;
        const __nv_bfloat16* Bs_h = gsm + (cur * 4 + 2) * 128 * GP;
        const __nv_bfloat16* Bs_l = gsm + (cur * 4 + 3) * 128 * GP;
#pragma unroll
        for (int kk = 0; kk < 2; kk++) {
            const int kc = kk * 16 + 2 * tig;
            unsigned ah[2][4], al[2][4];
#pragma unroll
            for (int mt = 0; mt < 2; mt++) {
                int row = wm + 16 * mt + gid;
                ah[mt][0] = *(const unsigned*)&As_h[row * GP + kc];
                ah[mt][1] = *(const unsigned*)&As_h[(row + 8) * GP + kc];
                ah[mt][2] = *(const unsigned*)&As_h[row * GP + kc + 8];
                ah[mt][3] = *(const unsigned*)&As_h[(row + 8) * GP + kc + 8];
                al[mt][0] = *(const unsigned*)&As_l[row * GP + kc];
                al[mt][1] = *(const unsigned*)&As_l[(row + 8) * GP + kc];
                al[mt][2] = *(const unsigned*)&As_l[row * GP + kc + 8];
                al[mt][3] = *(const unsigned*)&As_l[(row + 8) * GP + kc + 8];
            }
#pragma unroll
            for (int jn = 0; jn < 8; jn++) {
                int n = wn + 8 * jn + gid;
                unsigned bh0 = *(const unsigned*)&Bs_h[n * GP + kc];
                unsigned bh1 = *(const unsigned*)&Bs_h[n * GP + kc + 8];
                unsigned bl0 = *(const unsigned*)&Bs_l[n * GP + kc];
                unsigned bl1 = *(const unsigned*)&Bs_l[n * GP + kc + 8];
#pragma unroll
                for (int mt = 0; mt < 2; mt++) {
                    mma16816(acc[mt][jn], ah[mt], bh0, bh1);
                    mma16816(acc[mt][jn], ah[mt], bl0, bl1);
                    mma16816(acc[mt][jn], al[mt], bh0, bh1);
                }
            }
        }
        __syncthreads();
        if (kt + 2 < GEMM_NKT) load_stage(cur, kt + 2);
        CP_COMMIT();
    }

#pragma unroll
    for (int mt = 0; mt < 2; mt++) {
        int row0 = bm + wm + 16 * mt + gid;
#pragma unroll
        for (int jn = 0; jn < 8; jn++) {
            int col = bn + wn + 8 * jn + 2 * tig;
            float x0 = acc[mt][jn][0] * scale, x1 = acc[mt][jn][1] * scale;
            float x2 = acc[mt][jn][2] * scale, x3 = acc[mt][jn][3] * scale;
            if (mode == 0) {
                *(float2*)&Cf[(size_t)row0 * DIM + col] = make_float2(x0, x1);
                *(float2*)&Cf[(size_t)(row0 + 8) * DIM + col] = make_float2(x2, x3);
            } else {
                unsigned ph, pl;
                split_pack2(x0, x1, ph, pl);
                *(unsigned*)&Ch[(size_t)row0 * DIM + col] = ph;
                *(unsigned*)&Cl[(size_t)row0 * DIM + col] = pl;
                split_pack2(x2, x3, ph, pl);
                *(unsigned*)&Ch[(size_t)(row0 + 8) * DIM + col] = ph;
                *(unsigned*)&Cl[(size_t)(row0 + 8) * DIM + col] = pl;
            }
        }
    }
}

// ---------------- flash attention: MMA + cp.async KV + mask prefetch ---------
// Block: 256 thr (8 warps), Br=128 q rows, Bc=64 kv per iter, double-buffered.
#define AP 72
#define ATTN_NKT (T_SEQ / 64)
// smem: Qh/Ql 128*AP each + 2 stages x {Kh,Kl,Vh,Vl} 64*AP each
#define ATTN_SMEM ((2 * 128 + 8 * 64) * AP * 2)   // 110592 B

__global__ __launch_bounds__(256) void attn_mma(
    const __nv_bfloat16* __restrict__ Qh_, const __nv_bfloat16* __restrict__ Ql_,
    const __nv_bfloat16* __restrict__ Kh_, const __nv_bfloat16* __restrict__ Kl_,
    const __nv_bfloat16* __restrict__ Vth_, const __nv_bfloat16* __restrict__ Vtl_,
    const float* __restrict__ mask,
    __nv_bfloat16* __restrict__ Oh_, __nv_bfloat16* __restrict__ Ol_) {
    extern __shared__ __nv_bfloat16 asm_[];
    __nv_bfloat16* Qh = asm_;
    __nv_bfloat16* Ql = Qh + 128 * AP;
    __nv_bfloat16* KV = Ql + 128 * AP;  // stage s: 4 arrays x 64*AP

    const int tid = threadIdx.x;
    const int lane = tid & 31, wid = tid >> 5;
    const int gid = lane >> 2, tig = lane & 3;
    const int bq = blockIdx.x, h = blockIdx.y, b = blockIdx.z;
    const int bh = b * NH + h;
    const int qrow0 = b * T_SEQ + bq * 128;

    // KV stage loader via cp.async: arrays {Kh,Kl,Vh,Vl}
    auto load_kv = [&](int stage, int kt) {
        const int krow0 = b * T_SEQ + kt * 64;
        __nv_bfloat16* sb = KV + stage * 4 * 64 * AP;
#pragma unroll
        for (int i = tid; i < 2048; i += 256) {
            int a = i >> 9, r = (i >> 3) & 63, c = i & 7;
            __nv_bfloat16* dst = sb + a * 64 * AP + r * AP + c * 8;
            if (a == 0)
                cp16(dst, Kh_ + (size_t)(krow0 + r) * DIM + h * HS + c * 8);
            else if (a == 1)
                cp16(dst, Kl_ + (size_t)(krow0 + r) * DIM + h * HS + c * 8);
            else if (a == 2)
                cp16(dst, Vth_ + (size_t)(bh * HS + r) * T_SEQ + kt * 64 + c * 8);
            else
                cp16(dst, Vtl_ + (size_t)(bh * HS + r) * T_SEQ + kt * 64 + c * 8);
        }
    };

    // Q tile (regular loads, once)
#pragma unroll
    for (int i = tid; i < 128 * 8; i += 256) {
        int r = i >> 3, c8 = (i & 7) * 8;
        size_t g = (size_t)(qrow0 + r) * DIM + h * HS + c8;
        *(int4*)&Qh[r * AP + c8] = *(const int4*)&Qh_[g];
        *(int4*)&Ql[r * AP + c8] = *(const int4*)&Ql_[g];
    }

    load_kv(0, 0); CP_COMMIT();
    load_kv(1, 1); CP_COMMIT();

    float mi[2] = {-1e30f, -1e30f}, li[2] = {0.f, 0.f};
    float accO[8][4];
#pragma unroll
    for (int jn = 0; jn < 8; jn++)
#pragma unroll
        for (int e = 0; e < 4; e++) accO[jn][e] = 0.f;

    const int q0g = bq * 128 + 16 * wid + gid;
    const float* mrow = mask + (size_t)bh * T_SEQ * T_SEQ;
    __syncthreads();  // Q visible

    for (int kt = 0; kt < ATTN_NKT; kt++) {
        const int cur = kt & 1;
        CP_WAIT1();
        __syncthreads();
        const __nv_bfloat16* Kh_s = KV + (cur * 4 + 0) * 64 * AP;
        const __nv_bfloat16* Kl_s = KV + (cur * 4 + 1) * 64 * AP;
        const __nv_bfloat16* Vh_s = KV + (cur * 4 + 2) * 64 * AP;
        const __nv_bfloat16* Vl_s = KV + (cur * 4 + 3) * 64 * AP;

        // ---- mask prefetch (LDGs issued BEFORE the MMA asm block) ----
        float2 mr0[8], mr1[8];
#pragma unroll
        for (int jn = 0; jn < 8; jn++) {
            int c = kt * 64 + 8 * jn + 2 * tig;
            mr0[jn] = *(const float2*)&mrow[(size_t)q0g * T_SEQ + c];
            mr1[jn] = *(const float2*)&mrow[(size_t)(q0g + 8) * T_SEQ + c];
        }

        // ---- scores: S = Q @ K^T ----
        float sc[8][4];
#pragma unroll
        for (int jn = 0; jn < 8; jn++)
#pragma unroll
            for (int e = 0; e < 4; e++) sc[jn][e] = 0.f;
#pragma unroll
        for (int kk = 0; kk < 4; kk++) {
            const int kc = kk * 16 + 2 * tig;
            const int row = 16 * wid + gid;
            unsigned qah[4], qal[4];
            qah[0] = *(const unsigned*)&Qh[row * AP + kc];
            qah[1] = *(const unsigned*)&Qh[(row + 8) * AP + kc];
            qah[2] = *(const unsigned*)&Qh[row * AP + kc + 8];
            qah[3] = *(const unsigned*)&Qh[(row + 8) * AP + kc + 8];
            qal[0] = *(const unsigned*)&Ql[row * AP + kc];
            qal[1] = *(const unsigned*)&Ql[(row + 8) * AP + kc];
            qal[2] = *(const unsigned*)&Ql[row * AP + kc + 8];
            qal[3] = *(const unsigned*)&Ql[(row + 8) * AP + kc + 8];
#pragma unroll
            for (int jn = 0; jn < 8; jn++) {
                int n = 8 * jn + gid;
                unsigned bh0 = *(const unsigned*)&Kh_s[n * AP + kc];
                unsigned bh1 = *(const unsigned*)&Kh_s[n * AP + kc + 8];
                unsigned bl0 = *(const unsigned*)&Kl_s[n * AP + kc];
                unsigned bl1 = *(const unsigned*)&Kl_s[n * AP + kc + 8];
                mma16816(sc[jn], qah, bh0, bh1);
                mma16816(sc[jn], qah, bl0, bl1);
                mma16816(sc[jn], qal, bh0, bh1);
            }
        }

        // ---- apply mask from prefetched regs ----
#pragma unroll
        for (int jn = 0; jn < 8; jn++) {
            sc[jn][0] = fmaf(mr0[jn].x, NEG_INF_F, sc[jn][0]);
            sc[jn][1] = fmaf(mr0[jn].y, NEG_INF_F, sc[jn][1]);
            sc[jn][2] = fmaf(mr1[jn].x, NEG_INF_F, sc[jn][2]);
            sc[jn][3] = fmaf(mr1[jn].y, NEG_INF_F, sc[jn][3]);
        }

        // ---- online softmax ----
        float mx0 = -1e30f, mx1 = -1e30f;
#pragma unroll
        for (int jn = 0; jn < 8; jn++) {
            mx0 = fmaxf(mx0, fmaxf(sc[jn][0], sc[jn][1]));
            mx1 = fmaxf(mx1, fmaxf(sc[jn][2], sc[jn][3]));
        }
        mx0 = fmaxf(mx0, __shfl_xor_sync(0xffffffffu, mx0, 1));
        mx0 = fmaxf(mx0, __shfl_xor_sync(0xffffffffu, mx0, 2));
        mx1 = fmaxf(mx1, __shfl_xor_sync(0xffffffffu, mx1, 1));
        mx1 = fmaxf(mx1, __shfl_xor_sync(0xffffffffu, mx1, 2));
        float mn0 = fmaxf(mi[0], mx0), mn1 = fmaxf(mi[1], mx1);
        float corr0 = __expf(mi[0] - mn0), corr1 = __expf(mi[1] - mn1);
        mi[0] = mn0; mi[1] = mn1;
        float rs0 = 0.f, rs1 = 0.f;
#pragma unroll
        for (int jn = 0; jn < 8; jn++) {
            sc[jn][0] = __expf(sc[jn][0] - mn0); rs0 += sc[jn][0];
            sc[jn][1] = __expf(sc[jn][1] - mn0); rs0 += sc[jn][1];
            sc[jn][2] = __expf(sc[jn][2] - mn1); rs1 += sc[jn][2];
            sc[jn][3] = __expf(sc[jn][3] - mn1); rs1 += sc[jn][3];
        }
        rs0 += __shfl_xor_sync(0xffffffffu, rs0, 1);
        rs0 += __shfl_xor_sync(0xffffffffu, rs0, 2);
        rs1 += __shfl_xor_sync(0xffffffffu, rs1, 1);
        rs1 += __shfl_xor_sync(0xffffffffu, rs1, 2);
        li[0] = li[0] * corr0 + rs0;
        li[1] = li[1] * corr1 + rs1;
#pragma unroll
        for (int jn = 0; jn < 8; jn++) {
            accO[jn][0] *= corr0; accO[jn][1] *= corr0;
            accO[jn][2] *= corr1; accO[jn][3] *= corr1;
        }

        // ---- accO += P @ V (P fragments built in-register) ----
#pragma unroll
        for (int kk2 = 0; kk2 < 4; kk2++) {
            const int j0 = 2 * kk2, j1 = 2 * kk2 + 1;
            unsigned pah[4], pal[4];
            split_pack2(sc[j0][0], sc[j0][1], pah[0], pal[0]);
            split_pack2(sc[j0][2], sc[j0][3], pah[1], pal[1]);
            split_pack2(sc[j1][0], sc[j1][1], pah[2], pal[2]);
            split_pack2(sc[j1][2], sc[j1][3], pah[3], pal[3]);
            const int kc = kk2 * 16 + 2 * tig;
#pragma unroll
            for (int jn = 0; jn < 8; jn++) {
                int n = 8 * jn + gid;
                unsigned vh0 = *(const unsigned*)&Vh_s[n * AP + kc];
                unsigned vh1 = *(const unsigned*)&Vh_s[n * AP + kc + 8];
                unsigned vl0 = *(const unsigned*)&Vl_s[n * AP + kc];
                unsigned vl1 = *(const unsigned*)&Vl_s[n * AP + kc + 8];
                mma16816(accO[jn], pah, vh0, vh1);
                mma16816(accO[jn], pah, vl0, vl1);
                mma16816(accO[jn], pal, vh0, vh1);
            }
        }
        __syncthreads();
        if (kt + 2 < ATTN_NKT) load_kv(cur, kt + 2);
        CP_COMMIT();
    }

    // ---- epilogue ----
    const float inv0 = 1.f / li[0], inv1 = 1.f / li[1];
    const int row0 = qrow0 + 16 * wid + gid;
#pragma unroll
    for (int jn = 0; jn < 8; jn++) {
        int col = h * HS + 8 * jn + 2 * tig;
        unsigned ph, pl;
        split_pack2(accO[jn][0] * inv0, accO[jn][1] * inv0, ph, pl);
        *(unsigned*)&Oh_[(size_t)row0 * DIM + col] = ph;
        *(unsigned*)&Ol_[(size_t)row0 * DIM + col] = pl;
        split_pack2(accO[jn][2] * inv1, accO[jn][3] * inv1, ph, pl);
        *(unsigned*)&Oh_[(size_t)(row0 + 8) * DIM + col] = ph;
        *(unsigned*)&Ol_[(size_t)(row0 + 8) * DIM + col] = pl;
    }
}

// ---------------------------------------------------------------------------
extern "C" void kernel_launch(void* const* d_in, const int* in_sizes, int n_in,
                              void* d_out, int out_size) {
    const float* Xq   = (const float*)d_in[0];
    const float* Xr   = (const float*)d_in[1];
    const float* mask = (const float*)d_in[2];
    const float* Wq   = (const float*)d_in[3];
    const float* Wk   = (const float*)d_in[4];
    const float* Wv   = (const float*)d_in[5];
    const float* Wo   = (const float*)d_in[6];
    float* out = (float*)d_out;

    __nv_bfloat16 *Xqh, *Xql, *Xrh, *Xrl;
    __nv_bfloat16 *Wqh, *Wql, *Wkh, *Wkl, *Wvh, *Wvl, *Woh, *Wol;
    __nv_bfloat16 *Qh, *Ql, *Kh, *Kl, *Vh, *Vl, *Vth, *Vtl, *Oh, *Ol;
    cudaGetSymbolAddress((void**)&Xqh, g_Xqh); cudaGetSymbolAddress((void**)&Xql, g_Xql);
    cudaGetSymbolAddress((void**)&Xrh, g_Xrh); cudaGetSymbolAddress((void**)&Xrl, g_Xrl);
    cudaGetSymbolAddress((void**)&Wqh, g_Wqh); cudaGetSymbolAddress((void**)&Wql, g_Wql);
    cudaGetSymbolAddress((void**)&Wkh, g_Wkh); cudaGetSymbolAddress((void**)&Wkl, g_Wkl);
    cudaGetSymbolAddress((void**)&Wvh, g_Wvh); cudaGetSymbolAddress((void**)&Wvl, g_Wvl);
    cudaGetSymbolAddress((void**)&Woh, g_Woh); cudaGetSymbolAddress((void**)&Wol, g_Wol);
    cudaGetSymbolAddress((void**)&Qh, g_Qh);   cudaGetSymbolAddress((void**)&Ql, g_Ql);
    cudaGetSymbolAddress((void**)&Kh, g_Kh);   cudaGetSymbolAddress((void**)&Kl, g_Kl);
    cudaGetSymbolAddress((void**)&Vh, g_Vh);   cudaGetSymbolAddress((void**)&Vl, g_Vl);
    cudaGetSymbolAddress((void**)&Vth, g_Vth); cudaGetSymbolAddress((void**)&Vtl, g_Vtl);
    cudaGetSymbolAddress((void**)&Oh, g_Oh);   cudaGetSymbolAddress((void**)&Ol, g_Ol);

    cudaFuncSetAttribute(attn_mma, cudaFuncAttributeMaxDynamicSharedMemorySize, ATTN_SMEM);
    cudaFuncSetAttribute(gemm_mma, cudaFuncAttributeMaxDynamicSharedMemorySize, GEMM_SMEM);

    // 1) split inputs
    split_x<<<NELEM / 1024, 256>>>(Xq, Xqh, Xql);
    split_x<<<NELEM / 1024, 256>>>(Xr, Xrh, Xrl);
    dim3 gw(32, 32);
    split_wT<<<gw, 256>>>(Wq, Wqh, Wql);
    split_wT<<<gw, 256>>>(Wk, Wkh, Wkl);
    split_wT<<<gw, 256>>>(Wv, Wvh, Wvl);
    split_wT<<<gw, 256>>>(Wo, Woh, Wol);

    // 2) projections (split-bf16 outputs), Q scaled by S^-0.5
    dim3 gg(DIM / 128, NT_ROWS / 128);
    gemm_mma<<<gg, 256, GEMM_SMEM>>>(Xqh, Xql, Wqh, Wql, nullptr, Qh, Ql, 1, 0.125f);
    gemm_mma<<<gg, 256, GEMM_SMEM>>>(Xrh, Xrl, Wkh, Wkl, nullptr, Kh, Kl, 1, 1.0f);
    gemm_mma<<<gg, 256, GEMM_SMEM>>>(Xrh, Xrl, Wvh, Wvl, nullptr, Vh, Vl, 1, 1.0f);

    // 3) V transpose for PV fragment layout
    transpose_v<<<dim3(T_SEQ / 64, NB * NH), 256>>>(Vh, Vl, Vth, Vtl);

    // 4) flash attention
    attn_mma<<<dim3(T_SEQ / 128, NH, NB), 256, ATTN_SMEM>>>(
        Qh, Ql, Kh, Kl, Vth, Vtl, mask, Oh, Ol);

    // 5) output projection -> fp32 d_out
    gemm_mma<<<gg, 256, GEMM_SMEM>>>(Oh, Ol, Woh, Wol, out, nullptr, nullptr, 0, 1.0f);
}